// round 6
// baseline (speedup 1.0000x reference)
#include <cuda_runtime.h>
#include <cuda_fp16.h>
#include <stdint.h>
#include <math.h>

typedef __half fp16;

#define BB 8
#define SEQ 2048
#define DDIM 1024
#define MTOT (BB * SEQ)   // 16384

// ------------------------------------------------------------------
// PTX helpers (sm_80+ features only)
// ------------------------------------------------------------------
__device__ __forceinline__ uint32_t smem_u32(const void* p) {
    uint32_t a;
    asm("{ .reg .u64 t; cvta.to.shared.u64 t, %1; cvt.u32.u64 %0, t; }"
        : "=r"(a) : "l"(p));
    return a;
}
#define CP16(dst, src) \
    asm volatile("cp.async.cg.shared.global [%0], [%1], 16;" :: "r"(dst), "l"(src))
#define CP_COMMIT() asm volatile("cp.async.commit_group;" ::: "memory")
#define CP_WAIT1()  asm volatile("cp.async.wait_group 1;" ::: "memory")

__device__ __forceinline__ void ldmx4(uint32_t* r, uint32_t addr) {
    asm volatile("ldmatrix.sync.aligned.m8n8.x4.shared.b16 {%0,%1,%2,%3}, [%4];"
        : "=r"(r[0]), "=r"(r[1]), "=r"(r[2]), "=r"(r[3]) : "r"(addr));
}
__device__ __forceinline__ void ldmx4t(uint32_t* r, uint32_t addr) {
    asm volatile("ldmatrix.sync.aligned.m8n8.x4.trans.shared.b16 {%0,%1,%2,%3}, [%4];"
        : "=r"(r[0]), "=r"(r[1]), "=r"(r[2]), "=r"(r[3]) : "r"(addr));
}
__device__ __forceinline__ void mma16816(float* c, const uint32_t* a, const uint32_t* b) {
    asm("mma.sync.aligned.m16n8k16.row.col.f32.f16.f16.f32 "
        "{%0,%1,%2,%3}, {%4,%5,%6,%7}, {%8,%9}, {%0,%1,%2,%3};"
        : "+f"(c[0]), "+f"(c[1]), "+f"(c[2]), "+f"(c[3])
        : "r"(a[0]), "r"(a[1]), "r"(a[2]), "r"(a[3]), "r"(b[0]), "r"(b[1]));
}

// ------------------------------------------------------------------
// Scratch (static device globals; allocation forbidden)
// ------------------------------------------------------------------
__device__ fp16 g_iqh[(size_t)MTOT * DDIM], g_iql[(size_t)MTOT * DDIM];
__device__ fp16 g_ikh[(size_t)MTOT * DDIM], g_ikl[(size_t)MTOT * DDIM];
__device__ fp16 g_ivh[(size_t)MTOT * DDIM], g_ivl[(size_t)MTOT * DDIM];
__device__ fp16 g_wt[5][2][(size_t)DDIM * DDIM];
__device__ fp16 g_qh[(size_t)MTOT * DDIM], g_ql[(size_t)MTOT * DDIM];
__device__ fp16 g_kh[(size_t)MTOT * DDIM], g_kl[(size_t)MTOT * DDIM];
__device__ fp16 g_vh[(size_t)MTOT * DDIM], g_vl[(size_t)MTOT * DDIM];
__device__ float g_gate[(size_t)MTOT * DDIM];
__device__ float g_sc[(size_t)BB * SEQ * SEQ];
__device__ fp16 g_ph[(size_t)BB * SEQ * SEQ];
__device__ fp16 g_ch[(size_t)MTOT * DDIM], g_cl[(size_t)MTOT * DDIM];

// ------------------------------------------------------------------
// Elementwise split: fp32 -> hi(fp16), lo(fp16)
// ------------------------------------------------------------------
__global__ __launch_bounds__(256)
void split_f32(const float* __restrict__ x, fp16* __restrict__ h,
               fp16* __restrict__ l, size_t n)
{
    size_t i = ((size_t)blockIdx.x * 256 + threadIdx.x) * 4;
    if (i >= n) return;
    float4 v = *(const float4*)(x + i);
    fp16 h0 = __float2half(v.x), h1 = __float2half(v.y);
    fp16 h2 = __float2half(v.z), h3 = __float2half(v.w);
    __half2 hh0, hh1, ll0, ll1;
    hh0.x = h0; hh0.y = h1; hh1.x = h2; hh1.y = h3;
    ll0.x = __float2half(v.x - __half2float(h0));
    ll0.y = __float2half(v.y - __half2float(h1));
    ll1.x = __float2half(v.z - __half2float(h2));
    ll1.y = __float2half(v.w - __half2float(h3));
    *(__half2*)(h + i)     = hh0;
    *(__half2*)(h + i + 2) = hh1;
    *(__half2*)(l + i)     = ll0;
    *(__half2*)(l + i + 2) = ll1;
}

// ------------------------------------------------------------------
// Transpose + split: src [R,C] fp32 -> dst [C,R] hi/lo fp16 (weights)
// ------------------------------------------------------------------
__global__ __launch_bounds__(256)
void transpose_split(const float* __restrict__ src, fp16* __restrict__ dh,
                     fp16* __restrict__ dl, int R, int C)
{
    __shared__ float t[32][33];
    int r0 = blockIdx.y * 32, c0 = blockIdx.x * 32;
#pragma unroll
    for (int i = 0; i < 32; i += 8)
        t[threadIdx.y + i][threadIdx.x] =
            src[(size_t)(r0 + threadIdx.y + i) * C + c0 + threadIdx.x];
    __syncthreads();
#pragma unroll
    for (int i = 0; i < 32; i += 8) {
        int cc = c0 + threadIdx.y + i;
        int rr = r0 + threadIdx.x;
        float v = t[threadIdx.x][threadIdx.y + i];
        fp16 h = __float2half(v);
        dh[(size_t)cc * R + rr] = h;
        dl[(size_t)cc * R + rr] = __float2half(v - __half2float(h));
    }
}

// ------------------------------------------------------------------
// Register-resident row softmax: one read + one fp16 write.
// ------------------------------------------------------------------
__global__ __launch_bounds__(256)
void softmax_p(const float* __restrict__ Sc, fp16* __restrict__ Ph)
{
    __shared__ float red[8];
    const size_t row = blockIdx.x;
    const int tid  = threadIdx.x;
    const int lane = tid & 31;
    const int wrp  = tid >> 5;
    const float* p = Sc + row * SEQ;

    float r[8];
#pragma unroll
    for (int i = 0; i < 8; i++) r[i] = p[tid + i * 256];

    float m = r[0];
#pragma unroll
    for (int i = 1; i < 8; i++) m = fmaxf(m, r[i]);
#pragma unroll
    for (int o = 16; o > 0; o >>= 1)
        m = fmaxf(m, __shfl_xor_sync(0xFFFFFFFFu, m, o));
    if (lane == 0) red[wrp] = m;
    __syncthreads();
    float gm = red[0];
#pragma unroll
    for (int j = 1; j < 8; j++) gm = fmaxf(gm, red[j]);
    __syncthreads();

    float s = 0.0f;
#pragma unroll
    for (int i = 0; i < 8; i++) { r[i] = __expf(r[i] - gm); s += r[i]; }
#pragma unroll
    for (int o = 16; o > 0; o >>= 1)
        s += __shfl_xor_sync(0xFFFFFFFFu, s, o);
    if (lane == 0) red[wrp] = s;
    __syncthreads();
    float gs = red[0];
#pragma unroll
    for (int j = 1; j < 8; j++) gs += red[j];
    float inv = 1.0f / gs;

#pragma unroll
    for (int i = 0; i < 8; i++)
        Ph[row * SEQ + tid + i * 256] = __float2half(r[i] * inv);
}

// ------------------------------------------------------------------
// mma.sync fp16 split-emulated GEMM.
// bNN=0: C = A[M,K] @ B[N,K]^T   (B K-major, NT)
// bNN=1: C = A[M,K] @ B[K,N]     (B row-major, NN via ldmatrix.trans)
// mode 0: 3-pass A{hi,lo,hi} B{hi,hi,lo}
// mode 1: 2-pass A{hi,lo}    B{hi,hi}
// mode 2: 2-pass A{hi,hi}    B{hi,lo}
// mode 3: 1-pass A{hi}       B{hi}
// epi: 0=fp32, 1=bias fp32, 2=bias+split, 3=bias+sigmoid fp32, 4=gate*split
// ------------------------------------------------------------------
#define STAGES 3
#define STAGE_BYTES 32768
#define GEMM_SMEM (STAGES * STAGE_BYTES)

__global__ __launch_bounds__(256, 2)
void gemm3(const fp16* __restrict__ Ah, const fp16* __restrict__ Al,
           const fp16* __restrict__ Bh, const fp16* __restrict__ Bl,
           long long sAb, long long sBb, int K, int mode, int bNN, int ldb,
           float* __restrict__ Cf, fp16* __restrict__ Coh, fp16* __restrict__ Col,
           int ldc, long long sCb,
           const float* __restrict__ bias, const float* __restrict__ gate,
           long long sGb, int epi)
{
    extern __shared__ char dsm[];
    const uint32_t sbase = smem_u32(dsm);

    const int tid  = threadIdx.x;
    const int wid  = tid >> 5;
    const int lane = tid & 31;
    const int wm = wid >> 1;          // 0..3
    const int wn = wid & 1;           // 0..1
    const int z  = blockIdx.z;
    Ah += (long long)z * sAb; Al += (long long)z * sAb;
    Bh += (long long)z * sBb; Bl += (long long)z * sBb;

    const int m0 = blockIdx.y * 128;
    const int n0 = blockIdx.x * 128;
    const int KC = K >> 6;
    const int npass = (mode == 0) ? 3 : ((mode == 3) ? 1 : 2);
    const int NC = npass * KC;

    // A-tile loader slots (K-major, 128 rows x 8 chunks of 16B)
    int rows[4], cols[4];
    uint32_t soff[4];
    // NN B-tile loader slots (64 k-rows x 16 chunks of 16B)
    int rowsN[4], colsN[4];
    uint32_t soffN[4];
#pragma unroll
    for (int i = 0; i < 4; i++) {
        int idx = tid + i * 256;
        rows[i] = idx >> 3;
        cols[i] = idx & 7;
        soff[i] = (uint32_t)(rows[i] * 128 + ((cols[i] ^ (rows[i] & 7)) << 4));
        rowsN[i] = idx >> 4;
        colsN[i] = idx & 15;
        soffN[i] = (uint32_t)(rowsN[i] * 256 + ((colsN[i] ^ (rowsN[i] & 7)) << 4));
    }

    auto load_chunk = [&](int c, int stage) {
        int phase = c / KC;
        int inner = c - phase * KC;
        const fp16* As = Ah;
        const fp16* Bs = Bh;
        if (mode == 0) {
            if (phase == 1) As = Al;
            if (phase == 2) Bs = Bl;
        } else if (mode == 1) {
            if (phase == 1) As = Al;
        } else if (mode == 2) {
            if (phase == 1) Bs = Bl;
        }
        uint32_t aB = sbase + (uint32_t)stage * STAGE_BYTES;
        uint32_t bB = aB + 16384u;
#pragma unroll
        for (int i = 0; i < 4; i++)
            CP16(aB + soff[i], As + (size_t)(m0 + rows[i]) * K + inner * 64 + cols[i] * 8);
        if (bNN) {
#pragma unroll
            for (int i = 0; i < 4; i++)
                CP16(bB + soffN[i],
                     Bs + (size_t)(inner * 64 + rowsN[i]) * ldb + n0 + colsN[i] * 8);
        } else {
#pragma unroll
            for (int i = 0; i < 4; i++)
                CP16(bB + soff[i],
                     Bs + (size_t)(n0 + rows[i]) * K + inner * 64 + cols[i] * 8);
        }
    };

    // prologue: stages 0 and 1 in flight
    load_chunk(0, 0); CP_COMMIT();
    load_chunk(1, 1); CP_COMMIT();

    float acc[2][8][4];
#pragma unroll
    for (int mt = 0; mt < 2; mt++)
#pragma unroll
        for (int nt = 0; nt < 8; nt++)
#pragma unroll
            for (int r = 0; r < 4; r++) acc[mt][nt][r] = 0.0f;

    const int aRowBase = wm * 32 + (lane & 15);
    const int bRowBase = wn * 64 + (lane & 15);
    const int khalf    = lane >> 4;
    const int grp      = lane >> 3;      // NN-trans addressing
    const int gj       = lane & 7;

    for (int c = 0; c < NC; c++) {
        const int st = c % STAGES;
        CP_WAIT1();
        __syncthreads();
        if (c + 2 < NC) load_chunk(c + 2, (c + 2) % STAGES);
        CP_COMMIT();
        const uint32_t aB = sbase + (uint32_t)st * STAGE_BYTES;
        const uint32_t bB = aB + 16384u;
#pragma unroll
        for (int ks = 0; ks < 4; ks++) {
            const int ch = 2 * ks + khalf;
            uint32_t afr[2][4];
#pragma unroll
            for (int mt = 0; mt < 2; mt++) {
                int r = aRowBase + mt * 16;
                ldmx4(afr[mt], aB + (uint32_t)(r * 128 + ((ch ^ (r & 7)) << 4)));
            }
            uint32_t bfr[8][2];
            if (bNN) {
                const int krow = ks * 16 + (grp & 1) * 8 + gj;
#pragma unroll
                for (int nb = 0; nb < 4; nb++) {
                    int cc = wn * 8 + nb * 2 + (grp >> 1);
                    uint32_t t4[4];
                    ldmx4t(t4, bB + (uint32_t)(krow * 256 + ((cc ^ (krow & 7)) << 4)));
                    bfr[nb * 2][0]     = t4[0];
                    bfr[nb * 2][1]     = t4[1];
                    bfr[nb * 2 + 1][0] = t4[2];
                    bfr[nb * 2 + 1][1] = t4[3];
                }
            } else {
#pragma unroll
                for (int nb = 0; nb < 4; nb++) {
                    int r = bRowBase + nb * 16;
                    uint32_t t4[4];
                    ldmx4(t4, bB + (uint32_t)(r * 128 + ((ch ^ (r & 7)) << 4)));
                    bfr[nb * 2][0]     = t4[0];
                    bfr[nb * 2][1]     = t4[2];
                    bfr[nb * 2 + 1][0] = t4[1];
                    bfr[nb * 2 + 1][1] = t4[3];
                }
            }
#pragma unroll
            for (int mt = 0; mt < 2; mt++)
#pragma unroll
                for (int nt = 0; nt < 8; nt++)
                    mma16816(acc[mt][nt], afr[mt], bfr[nt]);
        }
    }

    // ---------------- epilogue ----------------
    const int erow0 = m0 + wm * 32 + (lane >> 2);
    const int ecol0 = n0 + wn * 64 + (lane & 3) * 2;

#pragma unroll
    for (int mt = 0; mt < 2; mt++) {
#pragma unroll
        for (int rr = 0; rr < 2; rr++) {
            const int row = erow0 + mt * 16 + rr * 8;
#pragma unroll
            for (int nt = 0; nt < 8; nt++) {
                const int col = ecol0 + nt * 8;
                float v0 = acc[mt][nt][2 * rr];
                float v1 = acc[mt][nt][2 * rr + 1];
                const size_t off = (size_t)z * sCb + (size_t)row * ldc + col;
                if (epi == 0) {
                    *(float2*)(Cf + off) = make_float2(v0, v1);
                } else if (epi == 1 || epi == 3) {
                    v0 += bias[col]; v1 += bias[col + 1];
                    if (epi == 3) {
                        v0 = 1.0f / (1.0f + __expf(-v0));
                        v1 = 1.0f / (1.0f + __expf(-v1));
                    }
                    *(float2*)(Cf + off) = make_float2(v0, v1);
                } else {
                    if (epi == 2) {
                        v0 += bias[col]; v1 += bias[col + 1];
                    } else {
                        float2 gg = *(const float2*)(gate + (size_t)z * sGb +
                                                     (size_t)row * ldc + col);
                        v0 *= gg.x; v1 *= gg.y;
                    }
                    fp16 h0 = __float2half(v0), h1 = __float2half(v1);
                    __half2 hh, ll;
                    hh.x = h0; hh.y = h1;
                    ll.x = __float2half(v0 - __half2float(h0));
                    ll.y = __float2half(v1 - __half2float(h1));
                    *(__half2*)(Coh + off) = hh;
                    *(__half2*)(Col + off) = ll;
                }
            }
        }
    }
}

// ------------------------------------------------------------------
// launch
// ------------------------------------------------------------------
extern "C" void kernel_launch(void* const* d_in, const int* in_sizes, int n_in,
                              void* d_out, int out_size)
{
    const float* queries = (const float*)d_in[0];
    const float* keys    = (const float*)d_in[1];
    const float* values  = (const float*)d_in[2];
    const float* Wq = (const float*)d_in[3];
    const float* bq = (const float*)d_in[4];
    const float* Wk = (const float*)d_in[5];
    const float* bk = (const float*)d_in[6];
    const float* Wv = (const float*)d_in[7];
    const float* bv = (const float*)d_in[8];
    const float* Wg = (const float*)d_in[9];
    const float* bg = (const float*)d_in[10];
    const float* Wo = (const float*)d_in[11];
    const float* bo = (const float*)d_in[12];
    float* out = (float*)d_out;

    fp16 *iqh, *iql, *ikh, *ikl, *ivh, *ivl, *wt;
    fp16 *qh, *ql, *kh, *kl, *vh, *vl, *ph, *ch, *cl;
    float *gate, *sc;
    cudaGetSymbolAddress((void**)&iqh, g_iqh); cudaGetSymbolAddress((void**)&iql, g_iql);
    cudaGetSymbolAddress((void**)&ikh, g_ikh); cudaGetSymbolAddress((void**)&ikl, g_ikl);
    cudaGetSymbolAddress((void**)&ivh, g_ivh); cudaGetSymbolAddress((void**)&ivl, g_ivl);
    cudaGetSymbolAddress((void**)&wt,  g_wt);
    cudaGetSymbolAddress((void**)&qh,  g_qh);  cudaGetSymbolAddress((void**)&ql,  g_ql);
    cudaGetSymbolAddress((void**)&kh,  g_kh);  cudaGetSymbolAddress((void**)&kl,  g_kl);
    cudaGetSymbolAddress((void**)&vh,  g_vh);  cudaGetSymbolAddress((void**)&vl,  g_vl);
    cudaGetSymbolAddress((void**)&gate, g_gate);
    cudaGetSymbolAddress((void**)&sc,  g_sc);
    cudaGetSymbolAddress((void**)&ph,  g_ph);
    cudaGetSymbolAddress((void**)&ch,  g_ch);  cudaGetSymbolAddress((void**)&cl,  g_cl);

    const size_t WSZ = (size_t)DDIM * DDIM;
    fp16* wth[5]; fp16* wtl[5];
    for (int w = 0; w < 5; w++) { wth[w] = wt + (2*w)*WSZ; wtl[w] = wt + (2*w+1)*WSZ; }

    cudaFuncSetAttribute(gemm3, cudaFuncAttributeMaxDynamicSharedMemorySize, GEMM_SMEM);

    const size_t nElem = (size_t)MTOT * DDIM;
    const int splitBlocks = (int)(nElem / 1024);
    dim3 tb(32, 8);
    dim3 gp(DDIM / 128, MTOT / 128, 1);

    // Launch order arranged so ncu (-s 5 -c 1) profiles the q-proj gemm3.
    transpose_split<<<dim3(32, 32), tb>>>(Wq, wth[0], wtl[0], DDIM, DDIM);   // 0
    transpose_split<<<dim3(32, 32), tb>>>(Wk, wth[1], wtl[1], DDIM, DDIM);   // 1
    split_f32<<<splitBlocks, 256>>>(queries, iqh, iql, nElem);               // 2
    split_f32<<<splitBlocks, 256>>>(keys,    ikh, ikl, nElem);               // 3
    split_f32<<<splitBlocks, 256>>>(values,  ivh, ivl, nElem);               // 4
    // 5: q proj (profiled) — 3-pass
    gemm3<<<gp, 256, GEMM_SMEM>>>(iqh, iql, wth[0], wtl[0], 0, 0, DDIM, 0, 0, 0,
                                  nullptr, qh, ql, DDIM, 0, bq, nullptr, 0, 2);
    transpose_split<<<dim3(32, 32), tb>>>(Wv, wth[2], wtl[2], DDIM, DDIM);   // 6
    transpose_split<<<dim3(32, 32), tb>>>(Wg, wth[3], wtl[3], DDIM, DDIM);   // 7
    transpose_split<<<dim3(32, 32), tb>>>(Wo, wth[4], wtl[4], DDIM, DDIM);   // 8
    // k proj — 3-pass
    gemm3<<<gp, 256, GEMM_SMEM>>>(ikh, ikl, wth[1], wtl[1], 0, 0, DDIM, 0, 0, 0,
                                  nullptr, kh, kl, DDIM, 0, bk, nullptr, 0, 2);
    // v proj — 2-pass (A-residual), write fp16 hi/lo [S,D] directly
    gemm3<<<gp, 256, GEMM_SMEM>>>(ivh, ivl, wth[2], wtl[2], 0, 0, DDIM, 1, 0, 0,
                                  nullptr, vh, vl, DDIM, 0, bv, nullptr, 0, 2);
    // gate proj — 1-pass (sigmoid compresses the error)
    gemm3<<<gp, 256, GEMM_SMEM>>>(iqh, iqh, wth[3], wth[3], 0, 0, DDIM, 3, 0, 0,
                                  gate, nullptr, nullptr, DDIM, 0, bg, nullptr, 0, 3);

    // scores = q @ k^T (per batch) — 3-pass NT
    gemm3<<<dim3(SEQ / 128, SEQ / 128, BB), 256, GEMM_SMEM>>>(
        qh, ql, kh, kl, (long long)SEQ * DDIM, (long long)SEQ * DDIM, DDIM, 0, 0, 0,
        sc, nullptr, nullptr, SEQ, (long long)SEQ * SEQ, nullptr, nullptr, 0, 0);

    // softmax -> fp16 P
    softmax_p<<<MTOT, 256>>>(sc, ph);

    // context = (P @ v) * gate -> split; 2-pass B-residual, NN B (ldmatrix.trans)
    gemm3<<<dim3(DDIM / 128, SEQ / 128, BB), 256, GEMM_SMEM>>>(
        ph, ph, vh, vl, (long long)SEQ * SEQ, (long long)SEQ * DDIM, SEQ, 2, 1, DDIM,
        nullptr, ch, cl, DDIM, (long long)SEQ * DDIM,
        nullptr, gate, (long long)SEQ * DDIM, 4);

    // out = ctx @ Wo + bo — 2-pass A-residual NT
    gemm3<<<gp, 256, GEMM_SMEM>>>(ch, cl, wth[4], wtl[4], 0, 0, DDIM, 1, 0, 0,
                                  out, nullptr, nullptr, DDIM, 0, bo, nullptr, 0, 1);
}

// round 7
// speedup vs baseline: 1.2650x; 1.2650x over previous
#include <cuda_runtime.h>
#include <cuda_fp16.h>
#include <stdint.h>
#include <math.h>

typedef __half fp16;

#define BB 8
#define SEQ 2048
#define DDIM 1024
#define MTOT (BB * SEQ)   // 16384

// ------------------------------------------------------------------
// PTX helpers (sm_80+ features only)
// ------------------------------------------------------------------
__device__ __forceinline__ uint32_t smem_u32(const void* p) {
    uint32_t a;
    asm("{ .reg .u64 t; cvta.to.shared.u64 t, %1; cvt.u32.u64 %0, t; }"
        : "=r"(a) : "l"(p));
    return a;
}
#define CP16(dst, src) \
    asm volatile("cp.async.cg.shared.global [%0], [%1], 16;" :: "r"(dst), "l"(src))
#define CP_COMMIT() asm volatile("cp.async.commit_group;" ::: "memory")
#define CP_WAIT1()  asm volatile("cp.async.wait_group 1;" ::: "memory")

__device__ __forceinline__ void ldmx4(uint32_t* r, uint32_t addr) {
    asm volatile("ldmatrix.sync.aligned.m8n8.x4.shared.b16 {%0,%1,%2,%3}, [%4];"
        : "=r"(r[0]), "=r"(r[1]), "=r"(r[2]), "=r"(r[3]) : "r"(addr));
}
__device__ __forceinline__ void mma16816(float* c, const uint32_t* a, const uint32_t* b) {
    asm("mma.sync.aligned.m16n8k16.row.col.f32.f16.f16.f32 "
        "{%0,%1,%2,%3}, {%4,%5,%6,%7}, {%8,%9}, {%0,%1,%2,%3};"
        : "+f"(c[0]), "+f"(c[1]), "+f"(c[2]), "+f"(c[3])
        : "r"(a[0]), "r"(a[1]), "r"(a[2]), "r"(a[3]), "r"(b[0]), "r"(b[1]));
}

// ------------------------------------------------------------------
// Scratch (static device globals; allocation forbidden)
// ------------------------------------------------------------------
__device__ fp16 g_iqh[(size_t)MTOT * DDIM], g_iql[(size_t)MTOT * DDIM];
__device__ fp16 g_ikh[(size_t)MTOT * DDIM], g_ikl[(size_t)MTOT * DDIM];
__device__ fp16 g_ivh[(size_t)MTOT * DDIM];
__device__ fp16 g_wt[5][2][(size_t)DDIM * DDIM];
__device__ fp16 g_qh[(size_t)MTOT * DDIM], g_ql[(size_t)MTOT * DDIM];
__device__ fp16 g_kh[(size_t)MTOT * DDIM], g_kl[(size_t)MTOT * DDIM];
__device__ float g_v[(size_t)MTOT * DDIM];
__device__ fp16 g_vth[(size_t)BB * DDIM * SEQ];
__device__ float g_gate[(size_t)MTOT * DDIM];
__device__ float g_sc[(size_t)BB * SEQ * SEQ];
__device__ fp16 g_ph[(size_t)BB * SEQ * SEQ];
__device__ fp16 g_ch[(size_t)MTOT * DDIM], g_cl[(size_t)MTOT * DDIM];

// ------------------------------------------------------------------
// Elementwise split: fp32 -> hi(fp16), lo(fp16)
// ------------------------------------------------------------------
__global__ __launch_bounds__(256)
void split_f32(const float* __restrict__ x, fp16* __restrict__ h,
               fp16* __restrict__ l, size_t n)
{
    size_t i = ((size_t)blockIdx.x * 256 + threadIdx.x) * 4;
    if (i >= n) return;
    float4 v = *(const float4*)(x + i);
    fp16 h0 = __float2half(v.x), h1 = __float2half(v.y);
    fp16 h2 = __float2half(v.z), h3 = __float2half(v.w);
    __half2 hh0, hh1, ll0, ll1;
    hh0.x = h0; hh0.y = h1; hh1.x = h2; hh1.y = h3;
    ll0.x = __float2half(v.x - __half2float(h0));
    ll0.y = __float2half(v.y - __half2float(h1));
    ll1.x = __float2half(v.z - __half2float(h2));
    ll1.y = __float2half(v.w - __half2float(h3));
    *(__half2*)(h + i)     = hh0;
    *(__half2*)(h + i + 2) = hh1;
    *(__half2*)(l + i)     = ll0;
    *(__half2*)(l + i + 2) = ll1;
}

// ------------------------------------------------------------------
// Elementwise convert: fp32 -> fp16 (hi only)
// ------------------------------------------------------------------
__global__ __launch_bounds__(256)
void conv_f16(const float* __restrict__ x, fp16* __restrict__ h, size_t n)
{
    size_t i = ((size_t)blockIdx.x * 256 + threadIdx.x) * 4;
    if (i >= n) return;
    float4 v = *(const float4*)(x + i);
    __half2 a, b;
    a.x = __float2half(v.x); a.y = __float2half(v.y);
    b.x = __float2half(v.z); b.y = __float2half(v.w);
    *(__half2*)(h + i)     = a;
    *(__half2*)(h + i + 2) = b;
}

// ------------------------------------------------------------------
// Transpose + split: src [R,C] fp32 -> dst [C,R] hi/lo fp16 (weights)
// ------------------------------------------------------------------
__global__ __launch_bounds__(256)
void transpose_split(const float* __restrict__ src, fp16* __restrict__ dh,
                     fp16* __restrict__ dl, int R, int C)
{
    __shared__ float t[32][33];
    int r0 = blockIdx.y * 32, c0 = blockIdx.x * 32;
#pragma unroll
    for (int i = 0; i < 32; i += 8)
        t[threadIdx.y + i][threadIdx.x] =
            src[(size_t)(r0 + threadIdx.y + i) * C + c0 + threadIdx.x];
    __syncthreads();
#pragma unroll
    for (int i = 0; i < 32; i += 8) {
        int cc = c0 + threadIdx.y + i;
        int rr = r0 + threadIdx.x;
        float v = t[threadIdx.x][threadIdx.y + i];
        fp16 h = __float2half(v);
        dh[(size_t)cc * R + rr] = h;
        dl[(size_t)cc * R + rr] = __float2half(v - __half2float(h));
    }
}

// ------------------------------------------------------------------
// Transpose (hi only): src [R,C] fp32 -> dst [C,R] fp16, batched
// ------------------------------------------------------------------
__global__ __launch_bounds__(256)
void transpose_h(const float* __restrict__ src, fp16* __restrict__ dh,
                 int R, int C, long long sb, long long db)
{
    __shared__ float t[32][33];
    src += (long long)blockIdx.z * sb;
    dh  += (long long)blockIdx.z * db;
    int r0 = blockIdx.y * 32, c0 = blockIdx.x * 32;
#pragma unroll
    for (int i = 0; i < 32; i += 8)
        t[threadIdx.y + i][threadIdx.x] =
            src[(size_t)(r0 + threadIdx.y + i) * C + c0 + threadIdx.x];
    __syncthreads();
#pragma unroll
    for (int i = 0; i < 32; i += 8) {
        int cc = c0 + threadIdx.y + i;
        int rr = r0 + threadIdx.x;
        dh[(size_t)cc * R + rr] = __float2half(t[threadIdx.x][threadIdx.y + i]);
    }
}

// ------------------------------------------------------------------
// Register-resident row softmax: one read + one fp16 write.
// ------------------------------------------------------------------
__global__ __launch_bounds__(256)
void softmax_p(const float* __restrict__ Sc, fp16* __restrict__ Ph)
{
    __shared__ float red[8];
    const size_t row = blockIdx.x;
    const int tid  = threadIdx.x;
    const int lane = tid & 31;
    const int wrp  = tid >> 5;
    const float* p = Sc + row * SEQ;

    float r[8];
#pragma unroll
    for (int i = 0; i < 8; i++) r[i] = p[tid + i * 256];

    float m = r[0];
#pragma unroll
    for (int i = 1; i < 8; i++) m = fmaxf(m, r[i]);
#pragma unroll
    for (int o = 16; o > 0; o >>= 1)
        m = fmaxf(m, __shfl_xor_sync(0xFFFFFFFFu, m, o));
    if (lane == 0) red[wrp] = m;
    __syncthreads();
    float gm = red[0];
#pragma unroll
    for (int j = 1; j < 8; j++) gm = fmaxf(gm, red[j]);
    __syncthreads();

    float s = 0.0f;
#pragma unroll
    for (int i = 0; i < 8; i++) { r[i] = __expf(r[i] - gm); s += r[i]; }
#pragma unroll
    for (int o = 16; o > 0; o >>= 1)
        s += __shfl_xor_sync(0xFFFFFFFFu, s, o);
    if (lane == 0) red[wrp] = s;
    __syncthreads();
    float gs = red[0];
#pragma unroll
    for (int j = 1; j < 8; j++) gs += red[j];
    float inv = 1.0f / gs;

#pragma unroll
    for (int i = 0; i < 8; i++)
        Ph[row * SEQ + tid + i * 256] = __float2half(r[i] * inv);
}

// ------------------------------------------------------------------
// mma.sync fp16 split-emulated GEMM: C[M,N] = A[M,K] @ B[N,K]^T (NT only)
// mode 0: 3-pass A{hi,lo,hi} B{hi,hi,lo}
// mode 1: 2-pass A{hi,lo}    B{hi,hi}
// mode 2: 2-pass A{hi,hi}    B{hi,lo}
// mode 3: 1-pass A{hi}       B{hi}
// epi: 0=fp32, 1=bias fp32, 2=bias+split, 3=bias+sigmoid fp32, 4=gate*split
// ------------------------------------------------------------------
#define STAGES 3
#define STAGE_BYTES 32768
#define GEMM_SMEM (STAGES * STAGE_BYTES)

__global__ __launch_bounds__(256, 2)
void gemm3(const fp16* __restrict__ Ah, const fp16* __restrict__ Al,
           const fp16* __restrict__ Bh, const fp16* __restrict__ Bl,
           long long sAb, long long sBb, int K, int mode,
           float* __restrict__ Cf, fp16* __restrict__ Coh, fp16* __restrict__ Col,
           int ldc, long long sCb,
           const float* __restrict__ bias, const float* __restrict__ gate,
           long long sGb, int epi)
{
    extern __shared__ char dsm[];
    const uint32_t sbase = smem_u32(dsm);

    const int tid  = threadIdx.x;
    const int wid  = tid >> 5;
    const int lane = tid & 31;
    const int wm = wid >> 1;          // 0..3
    const int wn = wid & 1;           // 0..1
    const int z  = blockIdx.z;
    Ah += (long long)z * sAb; Al += (long long)z * sAb;
    Bh += (long long)z * sBb; Bl += (long long)z * sBb;

    const int m0 = blockIdx.y * 128;
    const int n0 = blockIdx.x * 128;
    const int KC = K >> 6;
    const int npass = (mode == 0) ? 3 : ((mode == 3) ? 1 : 2);
    const int NC = npass * KC;

    int rows[4], cols[4];
    uint32_t soff[4];
#pragma unroll
    for (int i = 0; i < 4; i++) {
        int idx = tid + i * 256;
        rows[i] = idx >> 3;
        cols[i] = idx & 7;
        soff[i] = (uint32_t)(rows[i] * 128 + ((cols[i] ^ (rows[i] & 7)) << 4));
    }

    auto load_chunk = [&](int c, int stage) {
        int phase = c / KC;
        int inner = c - phase * KC;
        const fp16* As = Ah;
        const fp16* Bs = Bh;
        if (mode == 0) {
            if (phase == 1) As = Al;
            if (phase == 2) Bs = Bl;
        } else if (mode == 1) {
            if (phase == 1) As = Al;
        } else if (mode == 2) {
            if (phase == 1) Bs = Bl;
        }
        uint32_t aB = sbase + (uint32_t)stage * STAGE_BYTES;
        uint32_t bB = aB + 16384u;
#pragma unroll
        for (int i = 0; i < 4; i++)
            CP16(aB + soff[i], As + (size_t)(m0 + rows[i]) * K + inner * 64 + cols[i] * 8);
#pragma unroll
        for (int i = 0; i < 4; i++)
            CP16(bB + soff[i], Bs + (size_t)(n0 + rows[i]) * K + inner * 64 + cols[i] * 8);
    };

    // prologue: stages 0 and 1 in flight
    load_chunk(0, 0); CP_COMMIT();
    load_chunk(1, 1); CP_COMMIT();

    float acc[2][8][4];
#pragma unroll
    for (int mt = 0; mt < 2; mt++)
#pragma unroll
        for (int nt = 0; nt < 8; nt++)
#pragma unroll
            for (int r = 0; r < 4; r++) acc[mt][nt][r] = 0.0f;

    const int aRowBase = wm * 32 + (lane & 15);
    const int bRowBase = wn * 64 + (lane & 15);
    const int khalf    = lane >> 4;

    for (int c = 0; c < NC; c++) {
        const int st = c % STAGES;
        CP_WAIT1();
        __syncthreads();
        if (c + 2 < NC) load_chunk(c + 2, (c + 2) % STAGES);
        CP_COMMIT();
        const uint32_t aB = sbase + (uint32_t)st * STAGE_BYTES;
        const uint32_t bB = aB + 16384u;
#pragma unroll
        for (int ks = 0; ks < 4; ks++) {
            const int ch = 2 * ks + khalf;
            uint32_t afr[2][4];
#pragma unroll
            for (int mt = 0; mt < 2; mt++) {
                int r = aRowBase + mt * 16;
                ldmx4(afr[mt], aB + (uint32_t)(r * 128 + ((ch ^ (r & 7)) << 4)));
            }
            uint32_t bfr[8][2];
#pragma unroll
            for (int nb = 0; nb < 4; nb++) {
                int r = bRowBase + nb * 16;
                uint32_t t4[4];
                ldmx4(t4, bB + (uint32_t)(r * 128 + ((ch ^ (r & 7)) << 4)));
                bfr[nb * 2][0]     = t4[0];
                bfr[nb * 2][1]     = t4[2];
                bfr[nb * 2 + 1][0] = t4[1];
                bfr[nb * 2 + 1][1] = t4[3];
            }
#pragma unroll
            for (int mt = 0; mt < 2; mt++)
#pragma unroll
                for (int nt = 0; nt < 8; nt++)
                    mma16816(acc[mt][nt], afr[mt], bfr[nt]);
        }
    }

    // ---------------- epilogue ----------------
    const int erow0 = m0 + wm * 32 + (lane >> 2);
    const int ecol0 = n0 + wn * 64 + (lane & 3) * 2;

#pragma unroll
    for (int mt = 0; mt < 2; mt++) {
#pragma unroll
        for (int rr = 0; rr < 2; rr++) {
            const int row = erow0 + mt * 16 + rr * 8;
#pragma unroll
            for (int nt = 0; nt < 8; nt++) {
                const int col = ecol0 + nt * 8;
                float v0 = acc[mt][nt][2 * rr];
                float v1 = acc[mt][nt][2 * rr + 1];
                const size_t off = (size_t)z * sCb + (size_t)row * ldc + col;
                if (epi == 0) {
                    *(float2*)(Cf + off) = make_float2(v0, v1);
                } else if (epi == 1 || epi == 3) {
                    v0 += bias[col]; v1 += bias[col + 1];
                    if (epi == 3) {
                        v0 = 1.0f / (1.0f + __expf(-v0));
                        v1 = 1.0f / (1.0f + __expf(-v1));
                    }
                    *(float2*)(Cf + off) = make_float2(v0, v1);
                } else {
                    if (epi == 2) {
                        v0 += bias[col]; v1 += bias[col + 1];
                    } else {
                        float2 gg = *(const float2*)(gate + (size_t)z * sGb +
                                                     (size_t)row * ldc + col);
                        v0 *= gg.x; v1 *= gg.y;
                    }
                    fp16 h0 = __float2half(v0), h1 = __float2half(v1);
                    __half2 hh, ll;
                    hh.x = h0; hh.y = h1;
                    ll.x = __float2half(v0 - __half2float(h0));
                    ll.y = __float2half(v1 - __half2float(h1));
                    *(__half2*)(Coh + off) = hh;
                    *(__half2*)(Col + off) = ll;
                }
            }
        }
    }
}

// ------------------------------------------------------------------
// launch
// ------------------------------------------------------------------
extern "C" void kernel_launch(void* const* d_in, const int* in_sizes, int n_in,
                              void* d_out, int out_size)
{
    const float* queries = (const float*)d_in[0];
    const float* keys    = (const float*)d_in[1];
    const float* values  = (const float*)d_in[2];
    const float* Wq = (const float*)d_in[3];
    const float* bq = (const float*)d_in[4];
    const float* Wk = (const float*)d_in[5];
    const float* bk = (const float*)d_in[6];
    const float* Wv = (const float*)d_in[7];
    const float* bv = (const float*)d_in[8];
    const float* Wg = (const float*)d_in[9];
    const float* bg = (const float*)d_in[10];
    const float* Wo = (const float*)d_in[11];
    const float* bo = (const float*)d_in[12];
    float* out = (float*)d_out;

    fp16 *iqh, *iql, *ikh, *ikl, *ivh, *wt;
    fp16 *qh, *ql, *kh, *kl, *vth, *ph, *ch, *cl;
    float *v, *gate, *sc;
    cudaGetSymbolAddress((void**)&iqh, g_iqh); cudaGetSymbolAddress((void**)&iql, g_iql);
    cudaGetSymbolAddress((void**)&ikh, g_ikh); cudaGetSymbolAddress((void**)&ikl, g_ikl);
    cudaGetSymbolAddress((void**)&ivh, g_ivh);
    cudaGetSymbolAddress((void**)&wt,  g_wt);
    cudaGetSymbolAddress((void**)&qh,  g_qh);  cudaGetSymbolAddress((void**)&ql,  g_ql);
    cudaGetSymbolAddress((void**)&kh,  g_kh);  cudaGetSymbolAddress((void**)&kl,  g_kl);
    cudaGetSymbolAddress((void**)&v,   g_v);
    cudaGetSymbolAddress((void**)&vth, g_vth);
    cudaGetSymbolAddress((void**)&gate, g_gate);
    cudaGetSymbolAddress((void**)&sc,  g_sc);
    cudaGetSymbolAddress((void**)&ph,  g_ph);
    cudaGetSymbolAddress((void**)&ch,  g_ch);  cudaGetSymbolAddress((void**)&cl,  g_cl);

    const size_t WSZ = (size_t)DDIM * DDIM;
    fp16* wth[5]; fp16* wtl[5];
    for (int w = 0; w < 5; w++) { wth[w] = wt + (2*w)*WSZ; wtl[w] = wt + (2*w+1)*WSZ; }

    cudaFuncSetAttribute(gemm3, cudaFuncAttributeMaxDynamicSharedMemorySize, GEMM_SMEM);

    const size_t nElem = (size_t)MTOT * DDIM;
    const int splitBlocks = (int)(nElem / 1024);
    dim3 tb(32, 8);
    dim3 gp(DDIM / 128, MTOT / 128, 1);

    // input conversions
    split_f32<<<splitBlocks, 256>>>(queries, iqh, iql, nElem);
    split_f32<<<splitBlocks, 256>>>(keys,    ikh, ikl, nElem);
    conv_f16<<<splitBlocks, 256>>>(values,  ivh, nElem);

    // weight transposes
    transpose_split<<<dim3(32, 32), tb>>>(Wq, wth[0], wtl[0], DDIM, DDIM);
    transpose_split<<<dim3(32, 32), tb>>>(Wk, wth[1], wtl[1], DDIM, DDIM);
    transpose_split<<<dim3(32, 32), tb>>>(Wv, wth[2], wtl[2], DDIM, DDIM);
    transpose_split<<<dim3(32, 32), tb>>>(Wg, wth[3], wtl[3], DDIM, DDIM);
    transpose_split<<<dim3(32, 32), tb>>>(Wo, wth[4], wtl[4], DDIM, DDIM);

    // projections
    // q, k: full 3-pass (feed softmax logits; x32 error amplification)
    gemm3<<<gp, 256, GEMM_SMEM>>>(iqh, iql, wth[0], wtl[0], 0, 0, DDIM, 0,
                                  nullptr, qh, ql, DDIM, 0, bq, nullptr, 0, 2);
    gemm3<<<gp, 256, GEMM_SMEM>>>(ikh, ikl, wth[1], wtl[1], 0, 0, DDIM, 0,
                                  nullptr, kh, kl, DDIM, 0, bk, nullptr, 0, 2);
    // v: 1-pass (attention averaging keeps the error ~3e-4)
    gemm3<<<gp, 256, GEMM_SMEM>>>(ivh, ivh, wth[2], wth[2], 0, 0, DDIM, 3,
                                  v, nullptr, nullptr, DDIM, 0, bv, nullptr, 0, 1);
    // gate: 1-pass (sigmoid compresses the error)
    gemm3<<<gp, 256, GEMM_SMEM>>>(iqh, iqh, wth[3], wth[3], 0, 0, DDIM, 3,
                                  gate, nullptr, nullptr, DDIM, 0, bg, nullptr, 0, 3);

    // scores = q @ k^T (per batch), full 3-pass
    gemm3<<<dim3(SEQ / 128, SEQ / 128, BB), 256, GEMM_SMEM>>>(
        qh, ql, kh, kl, (long long)SEQ * DDIM, (long long)SEQ * DDIM, DDIM, 0,
        sc, nullptr, nullptr, SEQ, (long long)SEQ * SEQ, nullptr, nullptr, 0, 0);

    // softmax -> fp16 P
    softmax_p<<<MTOT, 256>>>(sc, ph);

    // transpose v per batch (hi only): [S,D] -> [D,S]
    transpose_h<<<dim3(DDIM / 32, SEQ / 32, BB), tb>>>(
        v, vth, SEQ, DDIM, (long long)SEQ * DDIM, (long long)SEQ * DDIM);

    // context = (P @ v) * gate -> split; 1-pass NT
    gemm3<<<dim3(DDIM / 128, SEQ / 128, BB), 256, GEMM_SMEM>>>(
        ph, ph, vth, vth, (long long)SEQ * SEQ, (long long)DDIM * SEQ, SEQ, 3,
        nullptr, ch, cl, DDIM, (long long)SEQ * DDIM,
        nullptr, gate, (long long)SEQ * DDIM, 4);

    // out = ctx @ Wo + bo; 2-pass A-residual NT
    gemm3<<<gp, 256, GEMM_SMEM>>>(ch, cl, wth[4], wtl[4], 0, 0, DDIM, 1,
                                  out, nullptr, nullptr, DDIM, 0, bo, nullptr, 0, 1);
}

// round 8
// speedup vs baseline: 1.3083x; 1.0342x over previous
#include <cuda_runtime.h>
#include <cuda_fp16.h>
#include <stdint.h>
#include <math.h>

typedef __half fp16;

#define BB 8
#define SEQ 2048
#define DDIM 1024
#define MTOT (BB * SEQ)   // 16384

// ------------------------------------------------------------------
// PTX helpers (sm_80+ features only)
// ------------------------------------------------------------------
__device__ __forceinline__ uint32_t smem_u32(const void* p) {
    uint32_t a;
    asm("{ .reg .u64 t; cvta.to.shared.u64 t, %1; cvt.u32.u64 %0, t; }"
        : "=r"(a) : "l"(p));
    return a;
}
#define CP16(dst, src) \
    asm volatile("cp.async.cg.shared.global [%0], [%1], 16;" :: "r"(dst), "l"(src))
#define CP_COMMIT() asm volatile("cp.async.commit_group;" ::: "memory")
#define CP_WAIT1()  asm volatile("cp.async.wait_group 1;" ::: "memory")

__device__ __forceinline__ void ldmx4(uint32_t* r, uint32_t addr) {
    asm volatile("ldmatrix.sync.aligned.m8n8.x4.shared.b16 {%0,%1,%2,%3}, [%4];"
        : "=r"(r[0]), "=r"(r[1]), "=r"(r[2]), "=r"(r[3]) : "r"(addr));
}
__device__ __forceinline__ void mma16816(float* c, const uint32_t* a, const uint32_t* b) {
    asm("mma.sync.aligned.m16n8k16.row.col.f32.f16.f16.f32 "
        "{%0,%1,%2,%3}, {%4,%5,%6,%7}, {%8,%9}, {%0,%1,%2,%3};"
        : "+f"(c[0]), "+f"(c[1]), "+f"(c[2]), "+f"(c[3])
        : "r"(a[0]), "r"(a[1]), "r"(a[2]), "r"(a[3]), "r"(b[0]), "r"(b[1]));
}

// ------------------------------------------------------------------
// Scratch (static device globals; allocation forbidden)
// ------------------------------------------------------------------
__device__ fp16 g_iqh[(size_t)MTOT * DDIM], g_iql[(size_t)MTOT * DDIM];
__device__ fp16 g_ikh[(size_t)MTOT * DDIM], g_ikl[(size_t)MTOT * DDIM];
__device__ fp16 g_ivh[(size_t)MTOT * DDIM];
__device__ fp16 g_wt[5][2][(size_t)DDIM * DDIM];
__device__ fp16 g_qh[(size_t)MTOT * DDIM], g_ql[(size_t)MTOT * DDIM];
__device__ fp16 g_kh[(size_t)MTOT * DDIM], g_kl[(size_t)MTOT * DDIM];
__device__ float g_v[(size_t)MTOT * DDIM];
__device__ fp16 g_vth[(size_t)BB * DDIM * SEQ];
__device__ float g_gate[(size_t)MTOT * DDIM];
__device__ float g_sc[(size_t)BB * SEQ * SEQ];
__device__ fp16 g_ph[(size_t)BB * SEQ * SEQ];
__device__ fp16 g_ch[(size_t)MTOT * DDIM];

// ------------------------------------------------------------------
// Elementwise split: fp32 -> hi(fp16), lo(fp16)
// ------------------------------------------------------------------
__global__ __launch_bounds__(256)
void split_f32(const float* __restrict__ x, fp16* __restrict__ h,
               fp16* __restrict__ l, size_t n)
{
    size_t i = ((size_t)blockIdx.x * 256 + threadIdx.x) * 4;
    if (i >= n) return;
    float4 v = *(const float4*)(x + i);
    fp16 h0 = __float2half(v.x), h1 = __float2half(v.y);
    fp16 h2 = __float2half(v.z), h3 = __float2half(v.w);
    __half2 hh0, hh1, ll0, ll1;
    hh0.x = h0; hh0.y = h1; hh1.x = h2; hh1.y = h3;
    ll0.x = __float2half(v.x - __half2float(h0));
    ll0.y = __float2half(v.y - __half2float(h1));
    ll1.x = __float2half(v.z - __half2float(h2));
    ll1.y = __float2half(v.w - __half2float(h3));
    *(__half2*)(h + i)     = hh0;
    *(__half2*)(h + i + 2) = hh1;
    *(__half2*)(l + i)     = ll0;
    *(__half2*)(l + i + 2) = ll1;
}

// ------------------------------------------------------------------
// Elementwise convert: fp32 -> fp16 (hi only)
// ------------------------------------------------------------------
__global__ __launch_bounds__(256)
void conv_f16(const float* __restrict__ x, fp16* __restrict__ h, size_t n)
{
    size_t i = ((size_t)blockIdx.x * 256 + threadIdx.x) * 4;
    if (i >= n) return;
    float4 v = *(const float4*)(x + i);
    __half2 a, b;
    a.x = __float2half(v.x); a.y = __float2half(v.y);
    b.x = __float2half(v.z); b.y = __float2half(v.w);
    *(__half2*)(h + i)     = a;
    *(__half2*)(h + i + 2) = b;
}

// ------------------------------------------------------------------
// Transpose + split: src [R,C] fp32 -> dst [C,R] hi/lo fp16 (weights)
// ------------------------------------------------------------------
__global__ __launch_bounds__(256)
void transpose_split(const float* __restrict__ src, fp16* __restrict__ dh,
                     fp16* __restrict__ dl, int R, int C)
{
    __shared__ float t[32][33];
    int r0 = blockIdx.y * 32, c0 = blockIdx.x * 32;
#pragma unroll
    for (int i = 0; i < 32; i += 8)
        t[threadIdx.y + i][threadIdx.x] =
            src[(size_t)(r0 + threadIdx.y + i) * C + c0 + threadIdx.x];
    __syncthreads();
#pragma unroll
    for (int i = 0; i < 32; i += 8) {
        int cc = c0 + threadIdx.y + i;
        int rr = r0 + threadIdx.x;
        float v = t[threadIdx.x][threadIdx.y + i];
        fp16 h = __float2half(v);
        dh[(size_t)cc * R + rr] = h;
        dl[(size_t)cc * R + rr] = __float2half(v - __half2float(h));
    }
}

// ------------------------------------------------------------------
// Transpose (hi only): src [R,C] fp32 -> dst [C,R] fp16, batched
// ------------------------------------------------------------------
__global__ __launch_bounds__(256)
void transpose_h(const float* __restrict__ src, fp16* __restrict__ dh,
                 int R, int C, long long sb, long long db)
{
    __shared__ float t[32][33];
    src += (long long)blockIdx.z * sb;
    dh  += (long long)blockIdx.z * db;
    int r0 = blockIdx.y * 32, c0 = blockIdx.x * 32;
#pragma unroll
    for (int i = 0; i < 32; i += 8)
        t[threadIdx.y + i][threadIdx.x] =
            src[(size_t)(r0 + threadIdx.y + i) * C + c0 + threadIdx.x];
    __syncthreads();
#pragma unroll
    for (int i = 0; i < 32; i += 8) {
        int cc = c0 + threadIdx.y + i;
        int rr = r0 + threadIdx.x;
        dh[(size_t)cc * R + rr] = __float2half(t[threadIdx.x][threadIdx.y + i]);
    }
}

// ------------------------------------------------------------------
// Register-resident row softmax: one read + one fp16 write.
// ------------------------------------------------------------------
__global__ __launch_bounds__(256)
void softmax_p(const float* __restrict__ Sc, fp16* __restrict__ Ph)
{
    __shared__ float red[8];
    const size_t row = blockIdx.x;
    const int tid  = threadIdx.x;
    const int lane = tid & 31;
    const int wrp  = tid >> 5;
    const float* p = Sc + row * SEQ;

    float r[8];
#pragma unroll
    for (int i = 0; i < 8; i++) r[i] = p[tid + i * 256];

    float m = r[0];
#pragma unroll
    for (int i = 1; i < 8; i++) m = fmaxf(m, r[i]);
#pragma unroll
    for (int o = 16; o > 0; o >>= 1)
        m = fmaxf(m, __shfl_xor_sync(0xFFFFFFFFu, m, o));
    if (lane == 0) red[wrp] = m;
    __syncthreads();
    float gm = red[0];
#pragma unroll
    for (int j = 1; j < 8; j++) gm = fmaxf(gm, red[j]);
    __syncthreads();

    float s = 0.0f;
#pragma unroll
    for (int i = 0; i < 8; i++) { r[i] = __expf(r[i] - gm); s += r[i]; }
#pragma unroll
    for (int o = 16; o > 0; o >>= 1)
        s += __shfl_xor_sync(0xFFFFFFFFu, s, o);
    if (lane == 0) red[wrp] = s;
    __syncthreads();
    float gs = red[0];
#pragma unroll
    for (int j = 1; j < 8; j++) gs += red[j];
    float inv = 1.0f / gs;

#pragma unroll
    for (int i = 0; i < 8; i++)
        Ph[row * SEQ + tid + i * 256] = __float2half(r[i] * inv);
}

// ------------------------------------------------------------------
// mma.sync fp16 split-emulated GEMM: C[M,N] = A[M,K] @ B[N,K]^T (NT only)
// mode 0: 3-pass A{hi,lo,hi} B{hi,hi,lo}
// mode 1: 2-pass A{hi,lo}    B{hi,hi}
// mode 2: 2-pass A{hi,hi}    B{hi,lo}
// mode 3: 1-pass A{hi}       B{hi}
// epi: 0=fp32, 1=bias fp32, 2=bias+split, 3=bias+sigmoid fp32,
//      4=gate*split, 5=gate*convert (hi only)
// ------------------------------------------------------------------
#define STAGES 3
#define STAGE_BYTES 32768
#define GEMM_SMEM (STAGES * STAGE_BYTES)

__global__ __launch_bounds__(256, 2)
void gemm3(const fp16* __restrict__ Ah, const fp16* __restrict__ Al,
           const fp16* __restrict__ Bh, const fp16* __restrict__ Bl,
           long long sAb, long long sBb, int K, int mode,
           float* __restrict__ Cf, fp16* __restrict__ Coh, fp16* __restrict__ Col,
           int ldc, long long sCb,
           const float* __restrict__ bias, const float* __restrict__ gate,
           long long sGb, int epi)
{
    extern __shared__ char dsm[];
    const uint32_t sbase = smem_u32(dsm);

    const int tid  = threadIdx.x;
    const int wid  = tid >> 5;
    const int lane = tid & 31;
    const int wm = wid >> 1;          // 0..3
    const int wn = wid & 1;           // 0..1
    const int z  = blockIdx.z;
    Ah += (long long)z * sAb; Al += (long long)z * sAb;
    Bh += (long long)z * sBb; Bl += (long long)z * sBb;

    const int m0 = blockIdx.y * 128;
    const int n0 = blockIdx.x * 128;
    const int KC = K >> 6;
    const int npass = (mode == 0) ? 3 : ((mode == 3) ? 1 : 2);
    const int NC = npass * KC;

    int rows[4], cols[4];
    uint32_t soff[4];
#pragma unroll
    for (int i = 0; i < 4; i++) {
        int idx = tid + i * 256;
        rows[i] = idx >> 3;
        cols[i] = idx & 7;
        soff[i] = (uint32_t)(rows[i] * 128 + ((cols[i] ^ (rows[i] & 7)) << 4));
    }

    auto load_chunk = [&](int c, int stage) {
        int phase = c / KC;
        int inner = c - phase * KC;
        const fp16* As = Ah;
        const fp16* Bs = Bh;
        if (mode == 0) {
            if (phase == 1) As = Al;
            if (phase == 2) Bs = Bl;
        } else if (mode == 1) {
            if (phase == 1) As = Al;
        } else if (mode == 2) {
            if (phase == 1) Bs = Bl;
        }
        uint32_t aB = sbase + (uint32_t)stage * STAGE_BYTES;
        uint32_t bB = aB + 16384u;
#pragma unroll
        for (int i = 0; i < 4; i++)
            CP16(aB + soff[i], As + (size_t)(m0 + rows[i]) * K + inner * 64 + cols[i] * 8);
#pragma unroll
        for (int i = 0; i < 4; i++)
            CP16(bB + soff[i], Bs + (size_t)(n0 + rows[i]) * K + inner * 64 + cols[i] * 8);
    };

    // prologue: stages 0 and 1 in flight
    load_chunk(0, 0); CP_COMMIT();
    load_chunk(1, 1); CP_COMMIT();

    float acc[2][8][4];
#pragma unroll
    for (int mt = 0; mt < 2; mt++)
#pragma unroll
        for (int nt = 0; nt < 8; nt++)
#pragma unroll
            for (int r = 0; r < 4; r++) acc[mt][nt][r] = 0.0f;

    const int aRowBase = wm * 32 + (lane & 15);
    const int bRowBase = wn * 64 + (lane & 15);
    const int khalf    = lane >> 4;

    for (int c = 0; c < NC; c++) {
        const int st = c % STAGES;
        CP_WAIT1();
        __syncthreads();
        if (c + 2 < NC) load_chunk(c + 2, (c + 2) % STAGES);
        CP_COMMIT();
        const uint32_t aB = sbase + (uint32_t)st * STAGE_BYTES;
        const uint32_t bB = aB + 16384u;
#pragma unroll
        for (int ks = 0; ks < 4; ks++) {
            const int ch = 2 * ks + khalf;
            uint32_t afr[2][4];
#pragma unroll
            for (int mt = 0; mt < 2; mt++) {
                int r = aRowBase + mt * 16;
                ldmx4(afr[mt], aB + (uint32_t)(r * 128 + ((ch ^ (r & 7)) << 4)));
            }
            uint32_t bfr[8][2];
#pragma unroll
            for (int nb = 0; nb < 4; nb++) {
                int r = bRowBase + nb * 16;
                uint32_t t4[4];
                ldmx4(t4, bB + (uint32_t)(r * 128 + ((ch ^ (r & 7)) << 4)));
                bfr[nb * 2][0]     = t4[0];
                bfr[nb * 2][1]     = t4[2];
                bfr[nb * 2 + 1][0] = t4[1];
                bfr[nb * 2 + 1][1] = t4[3];
            }
#pragma unroll
            for (int mt = 0; mt < 2; mt++)
#pragma unroll
                for (int nt = 0; nt < 8; nt++)
                    mma16816(acc[mt][nt], afr[mt], bfr[nt]);
        }
    }

    // ---------------- epilogue ----------------
    const int erow0 = m0 + wm * 32 + (lane >> 2);
    const int ecol0 = n0 + wn * 64 + (lane & 3) * 2;

#pragma unroll
    for (int mt = 0; mt < 2; mt++) {
#pragma unroll
        for (int rr = 0; rr < 2; rr++) {
            const int row = erow0 + mt * 16 + rr * 8;
#pragma unroll
            for (int nt = 0; nt < 8; nt++) {
                const int col = ecol0 + nt * 8;
                float v0 = acc[mt][nt][2 * rr];
                float v1 = acc[mt][nt][2 * rr + 1];
                const size_t off = (size_t)z * sCb + (size_t)row * ldc + col;
                if (epi == 0) {
                    *(float2*)(Cf + off) = make_float2(v0, v1);
                } else if (epi == 1 || epi == 3) {
                    v0 += bias[col]; v1 += bias[col + 1];
                    if (epi == 3) {
                        v0 = 1.0f / (1.0f + __expf(-v0));
                        v1 = 1.0f / (1.0f + __expf(-v1));
                    }
                    *(float2*)(Cf + off) = make_float2(v0, v1);
                } else if (epi == 5) {
                    float2 gg = *(const float2*)(gate + (size_t)z * sGb +
                                                 (size_t)row * ldc + col);
                    __half2 hh;
                    hh.x = __float2half(v0 * gg.x);
                    hh.y = __float2half(v1 * gg.y);
                    *(__half2*)(Coh + off) = hh;
                } else {
                    if (epi == 2) {
                        v0 += bias[col]; v1 += bias[col + 1];
                    } else {
                        float2 gg = *(const float2*)(gate + (size_t)z * sGb +
                                                     (size_t)row * ldc + col);
                        v0 *= gg.x; v1 *= gg.y;
                    }
                    fp16 h0 = __float2half(v0), h1 = __float2half(v1);
                    __half2 hh, ll;
                    hh.x = h0; hh.y = h1;
                    ll.x = __float2half(v0 - __half2float(h0));
                    ll.y = __float2half(v1 - __half2float(h1));
                    *(__half2*)(Coh + off) = hh;
                    *(__half2*)(Col + off) = ll;
                }
            }
        }
    }
}

// ------------------------------------------------------------------
// launch
// ------------------------------------------------------------------
extern "C" void kernel_launch(void* const* d_in, const int* in_sizes, int n_in,
                              void* d_out, int out_size)
{
    const float* queries = (const float*)d_in[0];
    const float* keys    = (const float*)d_in[1];
    const float* values  = (const float*)d_in[2];
    const float* Wq = (const float*)d_in[3];
    const float* bq = (const float*)d_in[4];
    const float* Wk = (const float*)d_in[5];
    const float* bk = (const float*)d_in[6];
    const float* Wv = (const float*)d_in[7];
    const float* bv = (const float*)d_in[8];
    const float* Wg = (const float*)d_in[9];
    const float* bg = (const float*)d_in[10];
    const float* Wo = (const float*)d_in[11];
    const float* bo = (const float*)d_in[12];
    float* out = (float*)d_out;

    fp16 *iqh, *iql, *ikh, *ikl, *ivh, *wt;
    fp16 *qh, *ql, *kh, *kl, *vth, *ph, *ch;
    float *v, *gate, *sc;
    cudaGetSymbolAddress((void**)&iqh, g_iqh); cudaGetSymbolAddress((void**)&iql, g_iql);
    cudaGetSymbolAddress((void**)&ikh, g_ikh); cudaGetSymbolAddress((void**)&ikl, g_ikl);
    cudaGetSymbolAddress((void**)&ivh, g_ivh);
    cudaGetSymbolAddress((void**)&wt,  g_wt);
    cudaGetSymbolAddress((void**)&qh,  g_qh);  cudaGetSymbolAddress((void**)&ql,  g_ql);
    cudaGetSymbolAddress((void**)&kh,  g_kh);  cudaGetSymbolAddress((void**)&kl,  g_kl);
    cudaGetSymbolAddress((void**)&v,   g_v);
    cudaGetSymbolAddress((void**)&vth, g_vth);
    cudaGetSymbolAddress((void**)&gate, g_gate);
    cudaGetSymbolAddress((void**)&sc,  g_sc);
    cudaGetSymbolAddress((void**)&ph,  g_ph);
    cudaGetSymbolAddress((void**)&ch,  g_ch);

    const size_t WSZ = (size_t)DDIM * DDIM;
    fp16* wth[5]; fp16* wtl[5];
    for (int w = 0; w < 5; w++) { wth[w] = wt + (2*w)*WSZ; wtl[w] = wt + (2*w+1)*WSZ; }

    cudaFuncSetAttribute(gemm3, cudaFuncAttributeMaxDynamicSharedMemorySize, GEMM_SMEM);

    const size_t nElem = (size_t)MTOT * DDIM;
    const int splitBlocks = (int)(nElem / 1024);
    dim3 tb(32, 8);
    dim3 gp(DDIM / 128, MTOT / 128, 1);

    // Launch order: gemm3 q-proj is launch index 5 (ncu -s 5 -c 1 profiles it)
    split_f32<<<splitBlocks, 256>>>(queries, iqh, iql, nElem);               // 0
    split_f32<<<splitBlocks, 256>>>(keys,    ikh, ikl, nElem);               // 1
    conv_f16<<<splitBlocks, 256>>>(values,  ivh, nElem);                     // 2
    transpose_split<<<dim3(32, 32), tb>>>(Wq, wth[0], wtl[0], DDIM, DDIM);   // 3
    transpose_split<<<dim3(32, 32), tb>>>(Wk, wth[1], wtl[1], DDIM, DDIM);   // 4
    // 5: q proj (profiled) — 3-pass
    gemm3<<<gp, 256, GEMM_SMEM>>>(iqh, iql, wth[0], wtl[0], 0, 0, DDIM, 0,
                                  nullptr, qh, ql, DDIM, 0, bq, nullptr, 0, 2);
    transpose_split<<<dim3(32, 32), tb>>>(Wv, wth[2], wtl[2], DDIM, DDIM);   // 6
    transpose_split<<<dim3(32, 32), tb>>>(Wg, wth[3], wtl[3], DDIM, DDIM);   // 7
    transpose_split<<<dim3(32, 32), tb>>>(Wo, wth[4], wtl[4], DDIM, DDIM);   // 8
    // k proj — 3-pass
    gemm3<<<gp, 256, GEMM_SMEM>>>(ikh, ikl, wth[1], wtl[1], 0, 0, DDIM, 0,
                                  nullptr, kh, kl, DDIM, 0, bk, nullptr, 0, 2);
    // v proj — 1-pass (attention averaging keeps error small)
    gemm3<<<gp, 256, GEMM_SMEM>>>(ivh, ivh, wth[2], wth[2], 0, 0, DDIM, 3,
                                  v, nullptr, nullptr, DDIM, 0, bv, nullptr, 0, 1);
    // gate proj — 1-pass (sigmoid compresses the error)
    gemm3<<<gp, 256, GEMM_SMEM>>>(iqh, iqh, wth[3], wth[3], 0, 0, DDIM, 3,
                                  gate, nullptr, nullptr, DDIM, 0, bg, nullptr, 0, 3);

    // scores = q @ k^T (per batch) — 3-pass
    gemm3<<<dim3(SEQ / 128, SEQ / 128, BB), 256, GEMM_SMEM>>>(
        qh, ql, kh, kl, (long long)SEQ * DDIM, (long long)SEQ * DDIM, DDIM, 0,
        sc, nullptr, nullptr, SEQ, (long long)SEQ * SEQ, nullptr, nullptr, 0, 0);

    // softmax -> fp16 P
    softmax_p<<<MTOT, 256>>>(sc, ph);

    // transpose v per batch (hi only): [S,D] -> [D,S]
    transpose_h<<<dim3(DDIM / 32, SEQ / 32, BB), tb>>>(
        v, vth, SEQ, DDIM, (long long)SEQ * DDIM, (long long)SEQ * DDIM);

    // context = (P @ v) * gate -> fp16 hi only; 1-pass
    gemm3<<<dim3(DDIM / 128, SEQ / 128, BB), 256, GEMM_SMEM>>>(
        ph, ph, vth, vth, (long long)SEQ * SEQ, (long long)DDIM * SEQ, SEQ, 3,
        nullptr, ch, nullptr, DDIM, (long long)SEQ * DDIM,
        nullptr, gate, (long long)SEQ * DDIM, 5);

    // out = ctx @ Wo + bo — 1-pass
    gemm3<<<gp, 256, GEMM_SMEM>>>(ch, ch, wth[4], wth[4], 0, 0, DDIM, 3,
                                  out, nullptr, nullptr, DDIM, 0, bo, nullptr, 0, 1);
}